// round 10
// baseline (speedup 1.0000x reference)
#include <cuda_runtime.h>
#include <math.h>
#include <stdint.h>

#define Bv    8
#define Tv    4096
#define DIN   64
#define DRES  1024
#define NCTA  128
#define NTH   512     // 16 warps: 4 k-quarter groups x (2 row-grp x 2 batch-half)

// h staging: [buf][batch-half][k][4 batches]; every word carries a parity LSB
__device__ float g_hbuf[2][2][DRES][4];

__device__ __forceinline__ void barn(int id, int cnt) {
    asm volatile("bar.sync %0, %1;" :: "r"(id), "r"(cnt) : "memory");
}
__device__ __forceinline__ void bar_arrive(int id, int cnt) {
    asm volatile("bar.arrive %0, %1;" :: "r"(id), "r"(cnt) : "memory");
}
__device__ __forceinline__ uint4 ldv4(const float* p) {
    uint4 v;
    asm volatile("ld.volatile.global.v4.u32 {%0,%1,%2,%3}, [%4];"
                 : "=r"(v.x), "=r"(v.y), "=r"(v.z), "=r"(v.w) : "l"(p));
    return v;
}
__device__ __forceinline__ void stv(float* p, unsigned v) {
    asm volatile("st.volatile.global.u32 [%0], %1;" :: "l"(p), "r"(v) : "memory");
}
__device__ __forceinline__ uint64_t pack2(float lo, float hi) {
    uint64_t r;
    asm("mov.b64 %0, {%1, %2};" : "=l"(r) : "f"(lo), "f"(hi));
    return r;
}
__device__ __forceinline__ void unpack2(float& lo, float& hi, uint64_t v) {
    asm("mov.b64 {%0, %1}, %2;" : "=f"(lo), "=f"(hi) : "l"(v));
}
__device__ __forceinline__ void fma2(uint64_t& d, uint64_t a, uint64_t b) {
    asm("fma.rn.f32x2 %0, %1, %2, %0;" : "+l"(d) : "l"(a), "l"(b));
}
__device__ __forceinline__ float fast_tanh(float x) {
    float e = __expf(2.0f * x);
    return 1.0f - __fdividef(2.0f, e + 1.0f);
}

__global__ void __launch_bounds__(NTH, 1) esn_kernel(
    const float* __restrict__ u,      // [B, T, DIN]
    const float* __restrict__ w_in,   // [DRES, DIN]
    const float* __restrict__ w,      // [DRES, DRES]
    const float* __restrict__ w_bias, // [DRES]
    float* __restrict__ out)          // [B, T, DRES]
{
    __shared__ float red[2][256];     // double-buffered, quarter-interleaved

    const int tid  = threadIdx.x;
    const int wrp  = tid >> 5;
    const int lane = tid & 31;
    const int q    = wrp >> 2;        // k-quarter group 0..3
    const int wq   = wrp & 3;         // sub = rg*2+bg
    const int rg   = wq >> 1;
    const int bg   = wq & 1;          // batch half (hbuf plane)
    const int r0   = rg * 4;
    const int b0   = bg * 4;
    const int cta  = blockIdx.x;
    const int r_base = cta * 8;
    const int kq   = q * 256 + lane;  // base k (m=0)
    const bool is_epi = (wrp < 2);    // epilogue warps

    // ---- W as row-paired f32x2 in registers for all steps ----
    uint64_t Wp[8][2];
    #pragma unroll
    for (int m = 0; m < 8; ++m)
        #pragma unroll
        for (int rp = 0; rp < 2; ++rp)
            Wp[m][rp] = pack2(
                w[(size_t)(r_base + r0 + 2*rp    ) * DRES + kq + m*32],
                w[(size_t)(r_base + r0 + 2*rp + 1) * DRES + kq + m*32]);

    float2 winreg[4];
    if (q == 3) {
        #pragma unroll
        for (int rr = 0; rr < 4; ++rr)
            winreg[rr] = *(const float2*)(w_in + (r_base + r0 + rr) * DIN + lane * 2);
    }

    // ---- epilogue constants (tid < 64, one output each) ----
    float biasr = 0.f;
    int hoff = 0;
    size_t ob = 0;
    if (tid < 64) {
        int tile = tid >> 4, idx = tid & 15;
        int rl = (tile >> 1) * 4 + (idx >> 2);
        int bb = (tile & 1) * 4 + (idx & 3);
        biasr = w_bias[r_base + rl];
        hoff  = ((bb >> 2) * DRES + r_base + rl) * 4 + (bb & 3);
        ob    = (size_t)bb * Tv * DRES + r_base + rl;
    }

    // post-tree-reduce value index owned by this (even) lane
    const int jred = ((lane >> 4) & 1) * 8 + ((lane >> 3) & 1) * 4
                   + ((lane >> 2) & 1) * 2 + ((lane >> 1) & 1);
    // quarter-interleaved red slot: epilogue reads float4 at tid*4
    const int rslot = ((wq * 16 + jred) << 2) + q;

    for (int t = 0; t < Tv; ++t) {
        // ---- input projection folded into acc BEFORE the h wait ----
        uint64_t acc[2][4];
        if (q == 3) {
            float2 uv[4];
            #pragma unroll
            for (int bb = 0; bb < 4; ++bb)
                uv[bb] = __ldcg((const float2*)(u + ((size_t)(b0 + bb) * Tv + t) * DIN
                                                  + lane * 2));
            float s16[16];
            #pragma unroll
            for (int rr = 0; rr < 4; ++rr)
                #pragma unroll
                for (int bb = 0; bb < 4; ++bb)
                    s16[rr * 4 + bb] = fmaf(winreg[rr].y, uv[bb].y,
                                            winreg[rr].x * uv[bb].x);
            #pragma unroll
            for (int rp = 0; rp < 2; ++rp)
                #pragma unroll
                for (int bb = 0; bb < 4; ++bb)
                    acc[rp][bb] = pack2(s16[(2*rp)*4 + bb], s16[(2*rp+1)*4 + bb]);
        } else {
            #pragma unroll
            for (int rp = 0; rp < 2; ++rp)
                #pragma unroll
                for (int bb = 0; bb < 4; ++bb) acc[rp][bb] = 0ull;
        }

        if (t > 0) {
            // ---- self-validating h spin: parity LSB per 32-bit word ----
            const float* hb = &g_hbuf[(t - 1) & 1][bg][0][0];
            const unsigned pe = (unsigned)((((t - 1) >> 1) & 1) ^ 1);
            uint4 h4[8];
            unsigned okm = 0;
            while (okm != 0xFFu) {
                #pragma unroll
                for (int m = 0; m < 8; ++m)
                    if (!((okm >> m) & 1u)) {
                        h4[m] = ldv4(hb + (size_t)(kq + m * 32) * 4);
                        unsigned y = pe ? (h4[m].x & h4[m].y & h4[m].z & h4[m].w)
                                        : (h4[m].x | h4[m].y | h4[m].z | h4[m].w);
                        okm |= ((y & 1u) == pe) ? (1u << m) : 0u;
                    }
            }

            #pragma unroll
            for (int m = 0; m < 8; ++m) {
                const float* hm = (const float*)&h4[m];
                #pragma unroll
                for (int b = 0; b < 4; ++b) {
                    uint64_t hr = pack2(hm[b], hm[b]);
                    fma2(acc[0][b], Wp[m][0], hr);
                    fma2(acc[1][b], Wp[m][1], hr);
                }
            }
        }

        float acc16[16];
        #pragma unroll
        for (int rp = 0; rp < 2; ++rp)
            #pragma unroll
            for (int b = 0; b < 4; ++b)
                unpack2(acc16[(2 * rp) * 4 + b], acc16[(2 * rp + 1) * 4 + b], acc[rp][b]);

        // ---- register-halving tree reduce (31 SHFL) ----
        #pragma unroll
        for (int i = 0; i < 16; ++i) acc16[i] += __shfl_xor_sync(~0u, acc16[i], 16);
        float v8[8];
        #pragma unroll
        for (int i = 0; i < 8; ++i) v8[i] = (lane & 16) ? acc16[i + 8] : acc16[i];
        #pragma unroll
        for (int i = 0; i < 8; ++i) v8[i] += __shfl_xor_sync(~0u, v8[i], 8);
        float v4[4];
        #pragma unroll
        for (int i = 0; i < 4; ++i) v4[i] = (lane & 8) ? v8[i + 4] : v8[i];
        #pragma unroll
        for (int i = 0; i < 4; ++i) v4[i] += __shfl_xor_sync(~0u, v4[i], 4);
        float v2[2];
        #pragma unroll
        for (int i = 0; i < 2; ++i) v2[i] = (lane & 4) ? v4[i + 2] : v4[i];
        #pragma unroll
        for (int i = 0; i < 2; ++i) v2[i] += __shfl_xor_sync(~0u, v2[i], 2);
        float v1 = (lane & 2) ? v2[1] : v2[0];
        v1 += __shfl_xor_sync(~0u, v1, 1);

        float* redt = &red[t & 1][0];
        if (!(lane & 1)) redt[rslot] = v1;

        // ---- decoupled handoff: producers arrive and run ahead ----
        if (!is_epi) {
            bar_arrive(15, NTH);
            continue;
        }
        barn(15, NTH);                             // epilogue waits for all STS

        // ---- epilogue: 64 threads, one output each; parity-tagged publish ----
        if (tid < 64) {
            float4 rv = *(const float4*)&redt[tid << 2];   // one LDS.128
            float s = (rv.x + rv.y) + (rv.z + rv.w);
            s = fast_tanh(s + biasr);
            const unsigned pw = (unsigned)(((t >> 1) & 1) ^ 1);
            unsigned su = (__float_as_uint(s) & ~1u) | pw;
            stv(&(&g_hbuf[t & 1][0][0][0])[hoff], su);     // self-validating word
            out[ob + (size_t)t * DRES] = __uint_as_float(su);
        }
    }
}

extern "C" void kernel_launch(void* const* d_in, const int* in_sizes, int n_in,
                              void* d_out, int out_size) {
    const float* u      = (const float*)d_in[0];
    const float* w_in   = (const float*)d_in[1];
    const float* w      = (const float*)d_in[2];
    const float* w_bias = (const float*)d_in[3];
    float* out = (float*)d_out;

    // zero hbuf: LSB=0 ≠ first-write parity 1, so stale data never validates
    void* hbufPtr = nullptr;
    cudaGetSymbolAddress(&hbufPtr, g_hbuf);
    cudaMemsetAsync(hbufPtr, 0, sizeof(float) * 2 * 2 * DRES * 4, 0);

    esn_kernel<<<NCTA, NTH>>>(u, w_in, w, w_bias, out);
}

// round 11
// speedup vs baseline: 1.6779x; 1.6779x over previous
#include <cuda_runtime.h>
#include <math.h>
#include <stdint.h>

#define Bv    8
#define Tv    4096
#define DIN   64
#define DRES  1024
#define NCTA  128
#define NTH   512     // 16 warps: 4 k-quarter groups x (2 row-grp x 2 batch-half)
#define NQ    4
#define CTAS_PER_Q (NCTA / NQ)

// h staging: [buf][batch-half][k][4 batches]
__device__ float g_hbuf[2][2][DRES][4];
// per-(quarter, replica, step) counters — 4 replicas/quarter, 16KB apart, rotate per step
__device__ int   g_flags[NQ * 4 * Tv];

__device__ __forceinline__ void barn(int id, int cnt) {
    asm volatile("bar.sync %0, %1;" :: "r"(id), "r"(cnt) : "memory");
}
__device__ __forceinline__ void bar_arrive(int id, int cnt) {
    asm volatile("bar.arrive %0, %1;" :: "r"(id), "r"(cnt) : "memory");
}
__device__ __forceinline__ int ld_acq(const int* p) {
    int v;
    asm volatile("ld.global.acquire.gpu.b32 %0, [%1];" : "=r"(v) : "l"(p) : "memory");
    return v;
}
__device__ __forceinline__ void red_release_add(int* p, int v) {
    asm volatile("red.release.gpu.global.add.s32 [%0], %1;" :: "l"(p), "r"(v) : "memory");
}
__device__ __forceinline__ uint64_t pack2(float lo, float hi) {
    uint64_t r;
    asm("mov.b64 %0, {%1, %2};" : "=l"(r) : "f"(lo), "f"(hi));
    return r;
}
__device__ __forceinline__ void unpack2(float& lo, float& hi, uint64_t v) {
    asm("mov.b64 {%0, %1}, %2;" : "=f"(lo), "=f"(hi) : "l"(v));
}
__device__ __forceinline__ void fma2(uint64_t& d, uint64_t a, uint64_t b) {
    asm("fma.rn.f32x2 %0, %1, %2, %0;" : "+l"(d) : "l"(a), "l"(b));
}
__device__ __forceinline__ float fast_tanh(float x) {
    float e = __expf(2.0f * x);
    return 1.0f - __fdividef(2.0f, e + 1.0f);
}

__global__ void __launch_bounds__(NTH, 1) esn_kernel(
    const float* __restrict__ u,      // [B, T, DIN]
    const float* __restrict__ w_in,   // [DRES, DIN]
    const float* __restrict__ w,      // [DRES, DRES]
    const float* __restrict__ w_bias, // [DRES]
    float* __restrict__ out)          // [B, T, DRES]
{
    __shared__ float red[2][256];     // double-buffered, quarter-interleaved

    const int tid  = threadIdx.x;
    const int wrp  = tid >> 5;
    const int lane = tid & 31;
    const int q    = wrp >> 2;        // k-quarter group 0..3
    const int wq   = wrp & 3;         // sub = rg*2+bg (also SMSP index)
    const int rg   = wq >> 1;
    const int bg   = wq & 1;          // batch half (hbuf plane)
    const int r0   = rg * 4;
    const int b0   = bg * 4;
    const int cta  = blockIdx.x;
    const int r_base = cta * 8;
    const int myq  = cta >> 5;        // quarter this CTA produces into
    const int kq   = q * 256 + lane;  // base k (m=0)
    const bool is_epi = (wrp < 2);    // epilogue warps (q=0, wq=0/1) — never pollers

    // ---- W as row-paired f32x2 in registers for all steps ----
    uint64_t Wp[8][2];
    #pragma unroll
    for (int m = 0; m < 8; ++m)
        #pragma unroll
        for (int rp = 0; rp < 2; ++rp)
            Wp[m][rp] = pack2(
                w[(size_t)(r_base + r0 + 2*rp    ) * DRES + kq + m*32],
                w[(size_t)(r_base + r0 + 2*rp + 1) * DRES + kq + m*32]);

    float2 winreg[4];
    if (q == 3) {
        #pragma unroll
        for (int rr = 0; rr < 4; ++rr)
            winreg[rr] = *(const float2*)(w_in + (r_base + r0 + rr) * DIN + lane * 2);
    }

    // ---- epilogue constants (tid < 64, one output each) ----
    float biasr = 0.f;
    int hoff = 0;
    size_t ob = 0;
    if (tid < 64) {
        int tile = tid >> 4, idx = tid & 15;
        int rl = (tile >> 1) * 4 + (idx >> 2);
        int bb = (tile & 1) * 4 + (idx & 3);
        biasr = w_bias[r_base + rl];
        hoff  = ((bb >> 2) * DRES + r_base + rl) * 4 + (bb & 3);
        ob    = (size_t)bb * Tv * DRES + r_base + rl;
    }

    // poll warp of group q = warp with wq == (q+2)&3 (never an epilogue warp);
    // it polls replica (cta & 3) of quarter q.
    const bool is_poll = (wq == ((q + 2) & 3));
    const int* const poll_base = &g_flags[(q * 4 + (cta & 3)) * Tv];
    // producer release targets: replicas 0..3 of quarter myq (tid 0-3)
    int* const rel_base = &g_flags[(myq * 4 + tid) * Tv];

    // post-tree-reduce value index owned by this (even) lane
    const int jred = ((lane >> 4) & 1) * 8 + ((lane >> 3) & 1) * 4
                   + ((lane >> 2) & 1) * 2 + ((lane >> 1) & 1);
    // quarter-interleaved red slot: epilogue reads one float4 at tid*4
    const int rslot = ((wq * 16 + jred) << 2) + q;

    for (int t = 0; t < Tv; ++t) {
        // ---- input projection folded into acc BEFORE the flag wait ----
        uint64_t acc[2][4];
        if (q == 3) {
            float2 uv[4];
            #pragma unroll
            for (int bb = 0; bb < 4; ++bb)
                uv[bb] = __ldcg((const float2*)(u + ((size_t)(b0 + bb) * Tv + t) * DIN
                                                  + lane * 2));
            float s16[16];
            #pragma unroll
            for (int rr = 0; rr < 4; ++rr)
                #pragma unroll
                for (int bb = 0; bb < 4; ++bb)
                    s16[rr * 4 + bb] = fmaf(winreg[rr].y, uv[bb].y,
                                            winreg[rr].x * uv[bb].x);
            #pragma unroll
            for (int rp = 0; rp < 2; ++rp)
                #pragma unroll
                for (int bb = 0; bb < 4; ++bb)
                    acc[rp][bb] = pack2(s16[(2*rp)*4 + bb], s16[(2*rp+1)*4 + bb]);
        } else {
            #pragma unroll
            for (int rp = 0; rp < 2; ++rp)
                #pragma unroll
                for (int bb = 0; bb < 4; ++bb) acc[rp][bb] = 0ull;
        }

        if (t > 0) {
            if (is_poll) {                         // one poller per quarter per CTA
                const int* fp = poll_base + (t - 1);
                while (ld_acq(fp) < CTAS_PER_Q) { }
            }
            barn(q + 1, 128);                      // propagate acquire to group

            // H quarter direct to registers (plane = batch half, full sectors)
            const float* hb = &g_hbuf[(t - 1) & 1][bg][0][0];
            float4 h4[8];
            #pragma unroll
            for (int m = 0; m < 8; ++m)
                h4[m] = __ldcg((const float4*)(hb + (size_t)(kq + m * 32) * 4));

            #pragma unroll
            for (int m = 0; m < 8; ++m) {
                const float* hm = (const float*)&h4[m];
                #pragma unroll
                for (int b = 0; b < 4; ++b) {
                    uint64_t hr = pack2(hm[b], hm[b]);
                    fma2(acc[0][b], Wp[m][0], hr);
                    fma2(acc[1][b], Wp[m][1], hr);
                }
            }
        }

        float acc16[16];
        #pragma unroll
        for (int rp = 0; rp < 2; ++rp)
            #pragma unroll
            for (int b = 0; b < 4; ++b)
                unpack2(acc16[(2 * rp) * 4 + b], acc16[(2 * rp + 1) * 4 + b], acc[rp][b]);

        // ---- register-halving tree reduce (31 SHFL) ----
        #pragma unroll
        for (int i = 0; i < 16; ++i) acc16[i] += __shfl_xor_sync(~0u, acc16[i], 16);
        float v8[8];
        #pragma unroll
        for (int i = 0; i < 8; ++i) v8[i] = (lane & 16) ? acc16[i + 8] : acc16[i];
        #pragma unroll
        for (int i = 0; i < 8; ++i) v8[i] += __shfl_xor_sync(~0u, v8[i], 8);
        float v4[4];
        #pragma unroll
        for (int i = 0; i < 4; ++i) v4[i] = (lane & 8) ? v8[i + 4] : v8[i];
        #pragma unroll
        for (int i = 0; i < 4; ++i) v4[i] += __shfl_xor_sync(~0u, v4[i], 4);
        float v2[2];
        #pragma unroll
        for (int i = 0; i < 2; ++i) v2[i] = (lane & 4) ? v4[i + 2] : v4[i];
        #pragma unroll
        for (int i = 0; i < 2; ++i) v2[i] += __shfl_xor_sync(~0u, v2[i], 2);
        float v1 = (lane & 2) ? v2[1] : v2[0];
        v1 += __shfl_xor_sync(~0u, v1, 1);

        float* redt = &red[t & 1][0];
        if (!(lane & 1)) redt[rslot] = v1;

        // ---- decoupled handoff: producers arrive and run ahead ----
        if (!is_epi) {
            bar_arrive(15, NTH);
            continue;                              // straight to next step
        }
        barn(15, NTH);                             // epilogue warps wait for all STS

        // ---- epilogue: 64 threads, one output each ----
        {
            float s = 0.f;
            if (tid < 64) {
                float4 rv = *(const float4*)&redt[tid << 2];   // one LDS.128
                s = (rv.x + rv.y) + (rv.z + rv.w);
                s = fast_tanh(s + biasr);
                (&g_hbuf[t & 1][0][0][0])[hoff] = s;
            }
            barn(9, 64);                           // hbuf stores ordered before flags
            if (tid < 4)
                red_release_add(rel_base + t, 1);  // 4 parallel REDs, distinct lines
            if (tid < 64)
                out[ob + (size_t)t * DRES] = s;    // off the critical path
        }
    }
}

extern "C" void kernel_launch(void* const* d_in, const int* in_sizes, int n_in,
                              void* d_out, int out_size) {
    const float* u      = (const float*)d_in[0];
    const float* w_in   = (const float*)d_in[1];
    const float* w      = (const float*)d_in[2];
    const float* w_bias = (const float*)d_in[3];
    float* out = (float*)d_out;

    void* flagsPtr = nullptr;
    cudaGetSymbolAddress(&flagsPtr, g_flags);
    cudaMemsetAsync(flagsPtr, 0, NQ * 4 * Tv * sizeof(int), 0);

    esn_kernel<<<NCTA, NTH>>>(u, w_in, w, w_bias, out);
}